// round 16
// baseline (speedup 1.0000x reference)
#include <cuda_runtime.h>
#include <cooperative_groups.h>

namespace cg = cooperative_groups;

#define N_QUBITS 15
#define N_LAYERS 4
#define BATCHN   64
#define NLOC     16384            // per-CTA amplitudes (2^14)
#define NTHREADS 1024
#define SMEM_BYTES (NLOC * sizeof(float2))   // 131072 B

// Exchange buffers: [batch][slot(2)][rank(2)][NLOC] float2, as float4 pairs
// (16B alignment for vector loads).
__device__ float4 g_xchg4[BATCHN * 2 * 2 * NLOC / 2];

// ---------------------------------------------------------------------------
// Factored rotation on register bit BIT of a 16-amp subcube.
// tf = type*2 + form: type 0=RX 1=RY 2=RZ; form 0: t=s/c, form 1: u=c/s.
// ---------------------------------------------------------------------------
template<int BIT>
__device__ __forceinline__ void rotfac16(float2* a, float t, int tf) {
  if (tf == 0) {          // RX /c
#pragma unroll
    for (int j = 0; j < 16; j++) if (((j >> BIT) & 1) == 0) {
      const int k = j | (1 << BIT);
      float2 A0 = a[j], A1 = a[k];
      a[j].x = fmaf( t, A1.y, A0.x);  a[j].y = fmaf(-t, A1.x, A0.y);
      a[k].x = fmaf( t, A0.y, A1.x);  a[k].y = fmaf(-t, A0.x, A1.y);
    }
  } else if (tf == 1) {   // RX /s
#pragma unroll
    for (int j = 0; j < 16; j++) if (((j >> BIT) & 1) == 0) {
      const int k = j | (1 << BIT);
      float2 A0 = a[j], A1 = a[k];
      a[j].x = fmaf(t, A0.x,  A1.y);  a[j].y = fmaf(t, A0.y, -A1.x);
      a[k].x = fmaf(t, A1.x,  A0.y);  a[k].y = fmaf(t, A1.y, -A0.x);
    }
  } else if (tf == 2) {   // RY /c
#pragma unroll
    for (int j = 0; j < 16; j++) if (((j >> BIT) & 1) == 0) {
      const int k = j | (1 << BIT);
      float2 A0 = a[j], A1 = a[k];
      a[j].x = fmaf(-t, A1.x, A0.x);  a[j].y = fmaf(-t, A1.y, A0.y);
      a[k].x = fmaf( t, A0.x, A1.x);  a[k].y = fmaf( t, A0.y, A1.y);
    }
  } else if (tf == 3) {   // RY /s
#pragma unroll
    for (int j = 0; j < 16; j++) if (((j >> BIT) & 1) == 0) {
      const int k = j | (1 << BIT);
      float2 A0 = a[j], A1 = a[k];
      a[j].x = fmaf(t, A0.x, -A1.x);  a[j].y = fmaf(t, A0.y, -A1.y);
      a[k].x = fmaf(t, A1.x,  A0.x);  a[k].y = fmaf(t, A1.y,  A0.y);
    }
  } else if (tf == 4) {   // RZ /c
#pragma unroll
    for (int j = 0; j < 16; j++) if (((j >> BIT) & 1) == 0) {
      const int k = j | (1 << BIT);
      float2 A0 = a[j], A1 = a[k];
      a[j].x = fmaf( t, A0.y, A0.x);  a[j].y = fmaf(-t, A0.x, A0.y);
      a[k].x = fmaf(-t, A1.y, A1.x);  a[k].y = fmaf( t, A1.x, A1.y);
    }
  } else {                // RZ /s
#pragma unroll
    for (int j = 0; j < 16; j++) if (((j >> BIT) & 1) == 0) {
      const int k = j | (1 << BIT);
      float2 A0 = a[j], A1 = a[k];
      a[j].x = fmaf(t, A0.x,  A0.y);  a[j].y = fmaf(t, A0.y, -A0.x);
      a[k].x = fmaf(t, A1.x, -A1.y);  a[k].y = fmaf(t, A1.y,  A1.x);
    }
  }
}

// Factored rotation on a lane-bit qubit (amp bit = lane bit LB), 16 regs.
template<int LB>
__device__ __forceinline__ void rot_lane_fac16(float2* a, float t, int tf, int lane) {
  const int cb = (lane >> LB) & 1;
  if (tf == 0) {          // RX /c
#pragma unroll
    for (int j = 0; j < 16; j++) {
      float px = __shfl_xor_sync(0xffffffffu, a[j].x, 1 << LB);
      float py = __shfl_xor_sync(0xffffffffu, a[j].y, 1 << LB);
      float nx = fmaf( t, py, a[j].x);
      float ny = fmaf(-t, px, a[j].y);
      a[j].x = nx; a[j].y = ny;
    }
  } else if (tf == 1) {   // RX /s
#pragma unroll
    for (int j = 0; j < 16; j++) {
      float px = __shfl_xor_sync(0xffffffffu, a[j].x, 1 << LB);
      float py = __shfl_xor_sync(0xffffffffu, a[j].y, 1 << LB);
      a[j].x = fmaf(t, a[j].x,  py);
      a[j].y = fmaf(t, a[j].y, -px);
    }
  } else if (tf == 2) {   // RY /c
    const float sg = cb ? t : -t;
#pragma unroll
    for (int j = 0; j < 16; j++) {
      float px = __shfl_xor_sync(0xffffffffu, a[j].x, 1 << LB);
      float py = __shfl_xor_sync(0xffffffffu, a[j].y, 1 << LB);
      a[j].x = fmaf(sg, px, a[j].x);
      a[j].y = fmaf(sg, py, a[j].y);
    }
  } else if (tf == 3) {   // RY /s
#pragma unroll
    for (int j = 0; j < 16; j++) {
      float px = __shfl_xor_sync(0xffffffffu, a[j].x, 1 << LB);
      float py = __shfl_xor_sync(0xffffffffu, a[j].y, 1 << LB);
      a[j].x = fmaf(t, a[j].x, cb ? px : -px);
      a[j].y = fmaf(t, a[j].y, cb ? py : -py);
    }
  } else if (tf == 4) {   // RZ /c: diagonal, no shfl
    const float tt = cb ? -t : t;
#pragma unroll
    for (int j = 0; j < 16; j++) {
      float nx = fmaf( tt, a[j].y, a[j].x);
      float ny = fmaf(-tt, a[j].x, a[j].y);
      a[j].x = nx; a[j].y = ny;
    }
  } else {                // RZ /s: diagonal, no shfl
#pragma unroll
    for (int j = 0; j < 16; j++) {
      float nx = fmaf(t, a[j].x, cb ? -a[j].y : a[j].y);
      float ny = fmaf(t, a[j].y, cb ?  a[j].x : -a[j].x);
      a[j].x = nx; a[j].y = ny;
    }
  }
}

template<int BC, int BT>
__device__ __forceinline__ void cnotl16(float2* a) {
#pragma unroll
  for (int j = 0; j < 16; j++) {
    if (((j >> BC) & 1) == 1 && ((j >> BT) & 1) == 0) {
      int k = j | (1 << BT);
      float2 t = a[j]; a[j] = a[k]; a[k] = t;
    }
  }
}

// Generic factored pair rotation: m = value with qubit label lbl, o = partner
// (label lbl^1); returns new value at label lbl.
__device__ __forceinline__ float2 rotp(float2 m, float2 o, float t,
                                       int f, int lbl) {
  float2 r;
  if (f == 0) {        // RX /c
    r.x = fmaf( t, o.y, m.x);  r.y = fmaf(-t, o.x, m.y);
  } else if (f == 1) { // RX /s
    r.x = fmaf(t, m.x,  o.y);  r.y = fmaf(t, m.y, -o.x);
  } else if (f == 2) { // RY /c
    float sg = lbl ? t : -t;
    r.x = fmaf(sg, o.x, m.x);  r.y = fmaf(sg, o.y, m.y);
  } else {             // RY /s
    r.x = fmaf(t, m.x, lbl ? o.x : -o.x);
    r.y = fmaf(t, m.y, lbl ? o.y : -o.y);
  }
  return r;
}

__device__ __forceinline__ float2 rotd(float2 m, float t, int f, int lbl) {
  float2 r;
  if (f == 4) {        // RZ /c
    float tt = lbl ? -t : t;
    r.x = fmaf( tt, m.y, m.x);  r.y = fmaf(-tt, m.x, m.y);
  } else {             // RZ /s
    r.x = fmaf(t, m.x, lbl ? -m.y : m.y);
    r.y = fmaf(t, m.y, lbl ?  m.x : -m.x);
  }
  return r;
}

// Local amp index i: 14 bits; local bit k <-> qubit (14 - k) (qubits 1..14).
// Qubit 0 <-> cluster rank. Class = (q0 label, q1 label).
__global__ void __launch_bounds__(NTHREADS, 1) __cluster_dims__(2, 1, 1)
qdarts_kernel(const float* __restrict__ x, const float* __restrict__ Pm,
              const float* __restrict__ Qm, const float* __restrict__ rotp_,
              const float* __restrict__ gum, float* __restrict__ out)
{
  extern __shared__ float2 SM[];   // NLOC float2, LINEAR layout

  __shared__ float st_t[N_LAYERS * N_QUBITS];
  __shared__ int   st_f[N_LAYERS * N_QUBITS];
  __shared__ float st_s[N_LAYERS * N_QUBITS];
  __shared__ float sw[N_QUBITS][2];
  __shared__ float sred[4];
  __shared__ float sS2;

  cg::cluster_group cluster = cg::this_cluster();
  const int tid  = threadIdx.x;
  const int b    = blockIdx.x >> 1;
  const int rank = blockIdx.x & 1;
  const int lane = tid & 31;

  // ---- Gate selection: argmax(P@Q + gumbel); store (t, variant, scale). ----
  if (tid < N_LAYERS * N_QUBITS) {
    const int ix = tid;
    float best = -1e30f; int gb = 0;
#pragma unroll
    for (int gg = 0; gg < 3; gg++) {
      float logit = 0.f;
#pragma unroll
      for (int k = 0; k < 4; k++)
        logit += Pm[ix * 4 + k] * Qm[(ix * 4 + k) * 3 + gg];
      float v = logit + gum[ix * 3 + gg];
      if (v > best) { best = v; gb = gg; }
    }
    float sv, cv;
    sincosf(0.5f * rotp_[ix], &sv, &cv);
    const bool formB = fabsf(sv) > fabsf(cv);
    st_f[ix] = gb * 2 + (formB ? 1 : 0);
    st_t[ix] = formB ? __fdividef(cv, sv) : __fdividef(sv, cv);
    st_s[ix] = formB ? sv : cv;
  }
  if (tid < N_QUBITS) {
    float sv, cv;
    sincosf(0.5f * x[b * N_QUBITS + tid], &sv, &cv);
    sw[tid][0] = cv; sw[tid][1] = sv;
  }
  if (tid < 4) sred[tid] = 0.f;
  __syncthreads();

  if (tid == 0) {
    float pr = 1.f;
#pragma unroll 1
    for (int i = 0; i < N_LAYERS * N_QUBITS; i++) pr *= st_s[i];
    sS2 = pr * pr;
  }

  // ---- Sweep A indexing: amp = (tb13<<13)|(j<<10)|(tmid<<1)|p ----
  // reg bits: j = {q2,q3,q4} (amp 12..10), p = q14 (amp 0); a-idx = (j<<1)|p.
  const int tb13 = (tid >> 9) & 1;       // amp bit13 = q1 label
  const int tmid = tid & 511;            // amp bits 9..1
  const int xA   = ((tb13 << 13) | (tmid << 1)) >> 1;   // float4 base index

  // ---- Sweep B indexing: amp = (wHi<<10)|(jb<<6)|(wLo<<5)|lane ----
  // reg jb = {q5..q8} (amp 9..6); wLo = q9 label (amp 5); lane = q10..q14.
  const int wHi = tid >> 6;
  const int wLo = (tid >> 5) & 1;
  const int baseB = (wHi << 10) | (wLo << 5) | lane;

  // Store-perm cascade for CNOT chain (10,11)(11,12)(12,13)(13,14) on lane.
  int u_ = lane;
  u_ ^= (u_ >> 1) & 8;
  u_ ^= (u_ >> 1) & 4;
  u_ ^= (u_ >> 1) & 2;
  u_ ^= (u_ >> 1) & 1;
  const int dstE = u_;
  const int e0 = dstE & 1;

  float pA = 0.f, pB = 0.f;

#pragma unroll 1
  for (int l = 0; l < N_LAYERS; l++) {
    const int g0 = l * N_QUBITS;
    float2 a[16];

    // ======== Sweep A: rotations q0,q1 (pair-on-load), q2..q4, q14 ========
    {
      const float t0 = st_t[g0];     const int f0 = st_f[g0];
      const float t1 = st_t[g0 + 1]; const int f1 = st_f[g0 + 1];
      const bool q0d = (f0 >= 4), q1d = (f1 >= 4);

      if (l == 0) {
        // Analytic product state; q0/q1 chain reduces to one complex z.
        float prefT = 1.f;
#pragma unroll
        for (int q = 5; q <= 13; q++)
          prefT *= sw[q][(tmid >> (13 - q)) & 1];
        float2 q1v;
        {
          float2 m1 = make_float2(sw[1][tb13], 0.f);
          float2 o1 = make_float2(sw[1][tb13 ^ 1], 0.f);
          q1v = q1d ? rotd(m1, t1, f1, tb13) : rotp(m1, o1, t1, f1, tb13);
        }
        float2 zm = make_float2(q1v.x * sw[0][rank], q1v.y * sw[0][rank]);
        float2 zo = make_float2(q1v.x * sw[0][rank ^ 1], q1v.y * sw[0][rank ^ 1]);
        float2 z = q0d ? rotd(zm, t0, f0, rank) : rotp(zm, zo, t0, f0, rank);
        const float w140 = sw[14][0], w141 = sw[14][1];
#pragma unroll
        for (int j = 0; j < 8; j++) {
          float fj = prefT * sw[2][(j >> 2) & 1] * sw[3][(j >> 1) & 1]
                           * sw[4][j & 1];
          float s0 = fj * w140, s1 = fj * w141;
          a[2 * j]     = make_float2(z.x * s0, z.y * s0);
          a[2 * j + 1] = make_float2(z.x * s1, z.y * s1);
        }
      } else {
        // Single-write exchange: BOTH halves come from gmem (own slot and
        // partner slot) — sweep B writes gmem only; SMEM carries only the
        // intra-layer A->B handoff.
        const size_t slotbase = (size_t)(b * 2 + ((l - 1) & 1)) * 2;
        const float4* OW4 = g_xchg4 + (slotbase + rank) * (NLOC / 2);
        const float4* PG4 = g_xchg4 + (slotbase + (rank ^ 1)) * (NLOC / 2);
        // p=0 amps: own chain = my buffer; p=1 amps: own chain = partner
        // (fused CNOT(14,0) role swap — compile-time by p).
#pragma unroll
        for (int j = 0; j < 8; j++) {
          const int xx = xA | (j << 9);
          float4 s0v = __ldcg(&OW4[xx]);
          float4 g0v = __ldcg(&PG4[xx]);
          float2 sA0 = make_float2(s0v.x, s0v.y), sA1 = make_float2(s0v.z, s0v.w);
          float2 gA0 = make_float2(g0v.x, g0v.y), gA1 = make_float2(g0v.z, g0v.w);
          float2 mO0, mO1, mP0, mP1;
          if (q1d) {
            mO0 = rotd(sA0, t1, f1, tb13);  mO1 = rotd(sA1, t1, f1, tb13);
            mP0 = rotd(gA0, t1, f1, tb13);  mP1 = rotd(gA1, t1, f1, tb13);
          } else {
            float4 s1v = __ldcg(&OW4[xx ^ 4096]);
            float4 g1v = __ldcg(&PG4[xx ^ 4096]);
            float2 sB0 = make_float2(s1v.x, s1v.y), sB1 = make_float2(s1v.z, s1v.w);
            float2 gB0 = make_float2(g1v.x, g1v.y), gB1 = make_float2(g1v.z, g1v.w);
            mO0 = rotp(sA0, sB0, t1, f1, tb13);
            mO1 = rotp(sA1, sB1, t1, f1, tb13);
            mP0 = rotp(gA0, gB0, t1, f1, tb13);
            mP1 = rotp(gA1, gB1, t1, f1, tb13);
          }
          if (q0d) {
            a[2 * j]     = rotd(mO0, t0, f0, rank);
            a[2 * j + 1] = rotd(mP1, t0, f0, rank);
          } else {
            a[2 * j]     = rotp(mO0, mP0, t0, f0, rank);
            a[2 * j + 1] = rotp(mP1, mO1, t0, f0, rank);
          }
        }
      }
      // Rotations q2 (a bit3), q3 (bit2), q4 (bit1), q14 (bit0 = p).
      rotfac16<3>(a, st_t[g0 + 2],  st_f[g0 + 2]);
      rotfac16<2>(a, st_t[g0 + 3],  st_f[g0 + 3]);
      rotfac16<1>(a, st_t[g0 + 4],  st_f[g0 + 4]);
      rotfac16<0>(a, st_t[g0 + 14], st_f[g0 + 14]);
      // CNOT(1,2): ctrl = q1 post-CNOT(0,1) = tb13^rank (warp-uniform branch);
      // tgt q2 = a bit3.  (Conjugated control compensates for C01 at store.)
      if ((tb13 ^ rank) != 0) {
#pragma unroll
        for (int j2 = 0; j2 < 8; j2++) {
          float2 t2 = a[j2]; a[j2] = a[j2 | 8]; a[j2 | 8] = t2;
        }
      }
      cnotl16<3, 2>(a);  // CNOT(2,3)
      cnotl16<2, 1>(a);  // CNOT(3,4)
      // Store with fold: CNOT(0,1) -> addr ^ (rank<<13).
      // NOTE: CNOT(4,5) is NOT folded here — its target q5's rotation runs
      // in sweep B; the CNOT is applied there AFTER R_q5 (ring order).
      float4* SM4w = (float4*)SM;
      const int xS = xA ^ (rank << 12);
#pragma unroll
      for (int j = 0; j < 8; j++) {
        SM4w[xS | (j << 9)] =
            make_float4(a[2 * j].x, a[2 * j].y, a[2 * j + 1].x, a[2 * j + 1].y);
      }
    }
    __syncthreads();

    // ======== Sweep B: rotations q9 (pair-on-load), q5..q8, q10..q13 ========
    {
      const float t9 = st_t[g0 + 9]; const int f9 = st_f[g0 + 9];
      if (f9 >= 4) {
#pragma unroll
        for (int jb = 0; jb < 16; jb++)
          a[jb] = rotd(SM[baseB | (jb << 6)], t9, f9, wLo);
      } else {
#pragma unroll
        for (int jb = 0; jb < 16; jb++) {
          float2 own = SM[baseB | (jb << 6)];
          float2 par = SM[(baseB ^ 32) | (jb << 6)];
          a[jb] = rotp(own, par, t9, f9, wLo);
        }
      }
      // Rotations q5 (jb bit3), q6 (bit2), q7 (bit1), q8 (bit0).
      rotfac16<3>(a, st_t[g0 + 5], st_f[g0 + 5]);
      rotfac16<2>(a, st_t[g0 + 6], st_f[g0 + 6]);
      rotfac16<1>(a, st_t[g0 + 7], st_f[g0 + 7]);
      rotfac16<0>(a, st_t[g0 + 8], st_f[g0 + 8]);
      // Rotations q10..q13 (lane bits 4..1).  (q14 handled in sweep A.)
      rot_lane_fac16<4>(a, st_t[g0 + 10], st_f[g0 + 10], lane);
      rot_lane_fac16<3>(a, st_t[g0 + 11], st_f[g0 + 11], lane);
      rot_lane_fac16<2>(a, st_t[g0 + 12], st_f[g0 + 12], lane);
      rot_lane_fac16<1>(a, st_t[g0 + 13], st_f[g0 + 13], lane);
      // CNOT(4,5): ctrl q4 = amp bit10 = wHi bit0 = tid bit6 (warp-uniform
      // branch); tgt q5 = jb bit3. Applied AFTER R_q5 — ring order correct.
      if (wHi & 1) {
#pragma unroll
        for (int j2 = 0; j2 < 8; j2++) {
          float2 t2 = a[j2]; a[j2] = a[j2 | 8]; a[j2 | 8] = t2;
        }
      }
      cnotl16<3, 2>(a);  // CNOT(5,6)
      cnotl16<2, 1>(a);  // CNOT(6,7)
      cnotl16<1, 0>(a);  // CNOT(7,8)
      // CNOT(8,9): addr bit5 = wLo ^ (jb&1).
      // CNOT(9,10): cascade pre-flip by ctrl = wLo ^ (jb&1) -> dst ^ 31.
      // CNOT(10,11)..(13,14): cascade (dstE).
      // CNOT(14,0): physical, fused in next sweep-A load roles / reduction.

      if (l < N_LAYERS - 1) {
        // Single write: gmem only (own slot). Next sweep A reads both slots.
        float2* xw = (float2*)(g_xchg4
                       + ((size_t)(b * 2 + (l & 1)) * 2 + rank) * (NLOC / 2));
#pragma unroll
        for (int jb = 0; jb < 16; jb++) {
          const int c = wLo ^ (jb & 1);
          const int i = (wHi << 10) | (jb << 6) | (c << 5)
                        | (dstE ^ (c ? 31 : 0));
          xw[i] = a[jb];
        }
        cluster.sync();
      } else {
        // |amp|^2 class reduction. Final q14 of reg jb = e0 ^ wLo ^ (jb&1);
        // q0 label flips (rank -> rank^1) when q14 = 1; q1 = tb13 (uniform).
        float pe = 0.f, po = 0.f;
#pragma unroll
        for (int jb = 0; jb < 16; jb++) {
          float p = fmaf(a[jb].x, a[jb].x, a[jb].y * a[jb].y);
          if (jb & 1) po += p; else pe += p;
        }
        const int g = e0 ^ wLo;    // q14 of even-jb amps
        pA = g ? po : pe;          // q0 label = rank
        pB = g ? pe : po;          // q0 label = rank^1
      }
    }
  }

  // ---- Reduce: full warp reduce (class meaning lane-uniform) -> CTA -> out --
#pragma unroll
  for (int o = 16; o > 0; o >>= 1) {
    pA += __shfl_xor_sync(0xffffffffu, pA, o);
    pB += __shfl_xor_sync(0xffffffffu, pB, o);
  }
  if (lane == 0) {
    atomicAdd(&sred[(rank << 1) | tb13], pA);
    atomicAdd(&sred[((rank ^ 1) << 1) | tb13], pB);
  }
  __syncthreads();

  if (rank == 1 && tid < 4) {
    float* dst = cluster.map_shared_rank(sred, 0);
    atomicAdd(dst + tid, sred[tid]);
  }
  cluster.sync();
  if (rank == 0 && tid < 4) out[b * 4 + tid] = sred[tid] * sS2;
}

extern "C" void kernel_launch(void* const* d_in, const int* in_sizes, int n_in,
                              void* d_out, int out_size) {
  const float* x    = (const float*)d_in[0];
  const float* P    = (const float*)d_in[1];
  const float* Q    = (const float*)d_in[2];
  const float* rotp = (const float*)d_in[3];
  const float* gum  = (const float*)d_in[4];
  cudaFuncSetAttribute(qdarts_kernel,
                       cudaFuncAttributeMaxDynamicSharedMemorySize,
                       (int)SMEM_BYTES);
  qdarts_kernel<<<BATCHN * 2, NTHREADS, SMEM_BYTES>>>(x, P, Q, rotp, gum,
                                                      (float*)d_out);
}

// round 17
// speedup vs baseline: 1.0484x; 1.0484x over previous
#include <cuda_runtime.h>
#include <cooperative_groups.h>

namespace cg = cooperative_groups;

#define N_QUBITS 15
#define N_LAYERS 4
#define BATCHN   64
#define NLOC     16384            // per-CTA amplitudes (2^14)
#define NTHREADS 1024
#define SMEM_BYTES (NLOC * sizeof(float2))   // 131072 B

// Exchange buffers: [batch][slot(2)][rank(2)][NLOC] float2, as float4 pairs.
__device__ float4 g_xchg4[BATCHN * 2 * 2 * NLOC / 2];

// ---- f32x2 packed-FMA helpers (bitwise identical to 2x fmaf) ----
__device__ __forceinline__ unsigned long long pk2(float a, float b) {
  unsigned long long r;
  asm("mov.b64 %0, {%1, %2};" : "=l"(r) : "f"(a), "f"(b));
  return r;
}
__device__ __forceinline__ float2 ffma2(unsigned long long c,
                                        unsigned long long v,
                                        unsigned long long ad) {
  unsigned long long r;
  asm("fma.rn.f32x2 %0, %1, %2, %3;" : "=l"(r) : "l"(c), "l"(v), "l"(ad));
  float2 o;
  asm("mov.b64 {%0, %1}, %2;" : "=f"(o.x), "=f"(o.y) : "l"(r));
  return o;
}
__device__ __forceinline__ unsigned long long pkf2(float2 v) {
  return pk2(v.x, v.y);
}

// ---------------------------------------------------------------------------
// Factored rotation on register bit BIT of a 16-amp subcube.
// tf = type*2 + form: type 0=RX 1=RY 2=RZ; form 0: t=s/c, form 1: u=c/s.
// ---------------------------------------------------------------------------
template<int BIT>
__device__ __forceinline__ void rotfac16(float2* a, float t, int tf) {
  if (tf == 0) {          // RX /c
#pragma unroll
    for (int j = 0; j < 16; j++) if (((j >> BIT) & 1) == 0) {
      const int k = j | (1 << BIT);
      float2 A0 = a[j], A1 = a[k];
      a[j].x = fmaf( t, A1.y, A0.x);  a[j].y = fmaf(-t, A1.x, A0.y);
      a[k].x = fmaf( t, A0.y, A1.x);  a[k].y = fmaf(-t, A0.x, A1.y);
    }
  } else if (tf == 1) {   // RX /s
#pragma unroll
    for (int j = 0; j < 16; j++) if (((j >> BIT) & 1) == 0) {
      const int k = j | (1 << BIT);
      float2 A0 = a[j], A1 = a[k];
      a[j].x = fmaf(t, A0.x,  A1.y);  a[j].y = fmaf(t, A0.y, -A1.x);
      a[k].x = fmaf(t, A1.x,  A0.y);  a[k].y = fmaf(t, A1.y, -A0.x);
    }
  } else if (tf == 2) {   // RY /c : packed FFMA2 (componentwise)
    const unsigned long long tp = pk2( t,  t);
    const unsigned long long tn = pk2(-t, -t);
#pragma unroll
    for (int j = 0; j < 16; j++) if (((j >> BIT) & 1) == 0) {
      const int k = j | (1 << BIT);
      unsigned long long P0 = pkf2(a[j]), P1 = pkf2(a[k]);
      a[j] = ffma2(tn, P1, P0);    // A0 - t*A1
      a[k] = ffma2(tp, P0, P1);    // A1 + t*A0
    }
  } else if (tf == 3) {   // RY /s : a[k] packed, a[j] scalar
    const unsigned long long tp = pk2(t, t);
#pragma unroll
    for (int j = 0; j < 16; j++) if (((j >> BIT) & 1) == 0) {
      const int k = j | (1 << BIT);
      float2 A0 = a[j], A1 = a[k];
      a[j].x = fmaf(t, A0.x, -A1.x);  a[j].y = fmaf(t, A0.y, -A1.y);
      a[k] = ffma2(tp, pkf2(A1), pkf2(A0));   // t*A1 + A0
    }
  } else if (tf == 4) {   // RZ /c
#pragma unroll
    for (int j = 0; j < 16; j++) if (((j >> BIT) & 1) == 0) {
      const int k = j | (1 << BIT);
      float2 A0 = a[j], A1 = a[k];
      a[j].x = fmaf( t, A0.y, A0.x);  a[j].y = fmaf(-t, A0.x, A0.y);
      a[k].x = fmaf(-t, A1.y, A1.x);  a[k].y = fmaf( t, A1.x, A1.y);
    }
  } else {                // RZ /s
#pragma unroll
    for (int j = 0; j < 16; j++) if (((j >> BIT) & 1) == 0) {
      const int k = j | (1 << BIT);
      float2 A0 = a[j], A1 = a[k];
      a[j].x = fmaf(t, A0.x,  A0.y);  a[j].y = fmaf(t, A0.y, -A0.x);
      a[k].x = fmaf(t, A1.x, -A1.y);  a[k].y = fmaf(t, A1.y,  A1.x);
    }
  }
}

// Factored rotation on a lane-bit qubit (amp bit = lane bit LB), 16 regs.
template<int LB>
__device__ __forceinline__ void rot_lane_fac16(float2* a, float t, int tf, int lane) {
  const int cb = (lane >> LB) & 1;
  if (tf == 0) {          // RX /c : a = (t,-t)*(py,px) + a  -> packed
    const unsigned long long cf = pk2(t, -t);
#pragma unroll
    for (int j = 0; j < 16; j++) {
      float px = __shfl_xor_sync(0xffffffffu, a[j].x, 1 << LB);
      float py = __shfl_xor_sync(0xffffffffu, a[j].y, 1 << LB);
      a[j] = ffma2(cf, pk2(py, px), pkf2(a[j]));
    }
  } else if (tf == 1) {   // RX /s
#pragma unroll
    for (int j = 0; j < 16; j++) {
      float px = __shfl_xor_sync(0xffffffffu, a[j].x, 1 << LB);
      float py = __shfl_xor_sync(0xffffffffu, a[j].y, 1 << LB);
      a[j].x = fmaf(t, a[j].x,  py);
      a[j].y = fmaf(t, a[j].y, -px);
    }
  } else if (tf == 2) {   // RY /c : packed
    const float sg = cb ? t : -t;
    const unsigned long long cf = pk2(sg, sg);
#pragma unroll
    for (int j = 0; j < 16; j++) {
      float px = __shfl_xor_sync(0xffffffffu, a[j].x, 1 << LB);
      float py = __shfl_xor_sync(0xffffffffu, a[j].y, 1 << LB);
      a[j] = ffma2(cf, pk2(px, py), pkf2(a[j]));
    }
  } else if (tf == 3) {   // RY /s
#pragma unroll
    for (int j = 0; j < 16; j++) {
      float px = __shfl_xor_sync(0xffffffffu, a[j].x, 1 << LB);
      float py = __shfl_xor_sync(0xffffffffu, a[j].y, 1 << LB);
      a[j].x = fmaf(t, a[j].x, cb ? px : -px);
      a[j].y = fmaf(t, a[j].y, cb ? py : -py);
    }
  } else if (tf == 4) {   // RZ /c: diagonal, no shfl
    const float tt = cb ? -t : t;
#pragma unroll
    for (int j = 0; j < 16; j++) {
      float nx = fmaf( tt, a[j].y, a[j].x);
      float ny = fmaf(-tt, a[j].x, a[j].y);
      a[j].x = nx; a[j].y = ny;
    }
  } else {                // RZ /s: diagonal, no shfl
#pragma unroll
    for (int j = 0; j < 16; j++) {
      float nx = fmaf(t, a[j].x, cb ? -a[j].y : a[j].y);
      float ny = fmaf(t, a[j].y, cb ?  a[j].x : -a[j].x);
      a[j].x = nx; a[j].y = ny;
    }
  }
}

template<int BC, int BT>
__device__ __forceinline__ void cnotl16(float2* a) {
#pragma unroll
  for (int j = 0; j < 16; j++) {
    if (((j >> BC) & 1) == 1 && ((j >> BT) & 1) == 0) {
      int k = j | (1 << BT);
      float2 t = a[j]; a[j] = a[k]; a[k] = t;
    }
  }
}

// Generic factored pair rotation: m = value with qubit label lbl, o = partner
// (label lbl^1); returns new value at label lbl.
__device__ __forceinline__ float2 rotp(float2 m, float2 o, float t,
                                       int f, int lbl) {
  float2 r;
  if (f == 0) {        // RX /c : packed (t,-t)*(o.y,o.x) + m
    r = ffma2(pk2(t, -t), pk2(o.y, o.x), pkf2(m));
  } else if (f == 1) { // RX /s
    r.x = fmaf(t, m.x,  o.y);  r.y = fmaf(t, m.y, -o.x);
  } else if (f == 2) { // RY /c : packed
    float sg = lbl ? t : -t;
    r = ffma2(pk2(sg, sg), pkf2(o), pkf2(m));
  } else {             // RY /s
    r.x = fmaf(t, m.x, lbl ? o.x : -o.x);
    r.y = fmaf(t, m.y, lbl ? o.y : -o.y);
  }
  return r;
}

__device__ __forceinline__ float2 rotd(float2 m, float t, int f, int lbl) {
  float2 r;
  if (f == 4) {        // RZ /c
    float tt = lbl ? -t : t;
    r.x = fmaf( tt, m.y, m.x);  r.y = fmaf(-tt, m.x, m.y);
  } else {             // RZ /s
    r.x = fmaf(t, m.x, lbl ? -m.y : m.y);
    r.y = fmaf(t, m.y, lbl ?  m.x : -m.x);
  }
  return r;
}

// Local amp index i: 14 bits; local bit k <-> qubit (14 - k) (qubits 1..14).
// Qubit 0 <-> cluster rank. Class = (q0 label, q1 label).
__global__ void __launch_bounds__(NTHREADS, 1) __cluster_dims__(2, 1, 1)
qdarts_kernel(const float* __restrict__ x, const float* __restrict__ Pm,
              const float* __restrict__ Qm, const float* __restrict__ rotp_,
              const float* __restrict__ gum, float* __restrict__ out)
{
  extern __shared__ float2 SM[];   // NLOC float2, LINEAR layout

  __shared__ float st_t[N_LAYERS * N_QUBITS];
  __shared__ int   st_f[N_LAYERS * N_QUBITS];
  __shared__ float st_s[N_LAYERS * N_QUBITS];
  __shared__ float sw[N_QUBITS][2];
  __shared__ float sred[4];
  __shared__ float sS2;

  cg::cluster_group cluster = cg::this_cluster();
  const int tid  = threadIdx.x;
  const int b    = blockIdx.x >> 1;
  const int rank = blockIdx.x & 1;
  const int lane = tid & 31;

  // ---- Gate selection: argmax(P@Q + gumbel); store (t, variant, scale). ----
  if (tid < N_LAYERS * N_QUBITS) {
    const int ix = tid;
    float best = -1e30f; int gb = 0;
#pragma unroll
    for (int gg = 0; gg < 3; gg++) {
      float logit = 0.f;
#pragma unroll
      for (int k = 0; k < 4; k++)
        logit += Pm[ix * 4 + k] * Qm[(ix * 4 + k) * 3 + gg];
      float v = logit + gum[ix * 3 + gg];
      if (v > best) { best = v; gb = gg; }
    }
    float sv, cv;
    sincosf(0.5f * rotp_[ix], &sv, &cv);
    const bool formB = fabsf(sv) > fabsf(cv);
    st_f[ix] = gb * 2 + (formB ? 1 : 0);
    st_t[ix] = formB ? __fdividef(cv, sv) : __fdividef(sv, cv);
    st_s[ix] = formB ? sv : cv;
  }
  if (tid < N_QUBITS) {
    float sv, cv;
    sincosf(0.5f * x[b * N_QUBITS + tid], &sv, &cv);
    sw[tid][0] = cv; sw[tid][1] = sv;
  }
  if (tid < 4) sred[tid] = 0.f;
  __syncthreads();

  if (tid == 0) {
    float pr = 1.f;
#pragma unroll 1
    for (int i = 0; i < N_LAYERS * N_QUBITS; i++) pr *= st_s[i];
    sS2 = pr * pr;
  }

  // ---- Sweep A indexing: amp = (tb13<<13)|(j<<10)|(tmid<<1)|p ----
  // reg bits: j = {q2,q3,q4} (amp 12..10), p = q14 (amp 0); a-idx = (j<<1)|p.
  const int tb13 = (tid >> 9) & 1;       // amp bit13 = q1 label
  const int tmid = tid & 511;            // amp bits 9..1
  const int xA   = ((tb13 << 13) | (tmid << 1)) >> 1;   // float4 base index

  // ---- Sweep B indexing: amp = (wHi<<10)|(jb<<6)|(wLo<<5)|lane ----
  // reg jb = {q5..q8} (amp 9..6); wLo = q9 label (amp 5); lane = q10..q14.
  const int wHi = tid >> 6;
  const int wLo = (tid >> 5) & 1;
  const int baseB = (wHi << 10) | (wLo << 5) | lane;

  // Store-perm cascade for CNOT chain (10,11)(11,12)(12,13)(13,14) on lane.
  int u_ = lane;
  u_ ^= (u_ >> 1) & 8;
  u_ ^= (u_ >> 1) & 4;
  u_ ^= (u_ >> 1) & 2;
  u_ ^= (u_ >> 1) & 1;
  const int dstE = u_;
  const int e0 = dstE & 1;

  float pA = 0.f, pB = 0.f;

#pragma unroll 1
  for (int l = 0; l < N_LAYERS; l++) {
    const int g0 = l * N_QUBITS;
    float2 a[16];

    // ======== Sweep A: rotations q0,q1 (pair-on-load), q2..q4, q14 ========
    {
      const float t0 = st_t[g0];     const int f0 = st_f[g0];
      const float t1 = st_t[g0 + 1]; const int f1 = st_f[g0 + 1];
      const bool q0d = (f0 >= 4), q1d = (f1 >= 4);

      if (l == 0) {
        // Analytic product state; q0/q1 chain reduces to one complex z.
        float prefT = 1.f;
#pragma unroll
        for (int q = 5; q <= 13; q++)
          prefT *= sw[q][(tmid >> (13 - q)) & 1];
        float2 q1v;
        {
          float2 m1 = make_float2(sw[1][tb13], 0.f);
          float2 o1 = make_float2(sw[1][tb13 ^ 1], 0.f);
          q1v = q1d ? rotd(m1, t1, f1, tb13) : rotp(m1, o1, t1, f1, tb13);
        }
        float2 zm = make_float2(q1v.x * sw[0][rank], q1v.y * sw[0][rank]);
        float2 zo = make_float2(q1v.x * sw[0][rank ^ 1], q1v.y * sw[0][rank ^ 1]);
        float2 z = q0d ? rotd(zm, t0, f0, rank) : rotp(zm, zo, t0, f0, rank);
        const float w140 = sw[14][0], w141 = sw[14][1];
#pragma unroll
        for (int j = 0; j < 8; j++) {
          float fj = prefT * sw[2][(j >> 2) & 1] * sw[3][(j >> 1) & 1]
                           * sw[4][j & 1];
          float s0 = fj * w140, s1 = fj * w141;
          a[2 * j]     = make_float2(z.x * s0, z.y * s0);
          a[2 * j + 1] = make_float2(z.x * s1, z.y * s1);
        }
      } else {
        const float4* SM4 = (const float4*)SM;
        const float4* PG4 = g_xchg4 + ((size_t)(b * 2 + ((l - 1) & 1)) * 2
                                       + (rank ^ 1)) * (NLOC / 2);
        // p=0 amps: own chain = my SMEM; p=1 amps: own chain = partner
        // (fused CNOT(14,0) role swap — compile-time by p).
#pragma unroll
        for (int j = 0; j < 8; j++) {
          const int xx = xA | (j << 9);
          float4 s0v = SM4[xx];
          float4 g0v = __ldcg(&PG4[xx]);
          float2 sA0 = make_float2(s0v.x, s0v.y), sA1 = make_float2(s0v.z, s0v.w);
          float2 gA0 = make_float2(g0v.x, g0v.y), gA1 = make_float2(g0v.z, g0v.w);
          float2 mO0, mO1, mP0, mP1;
          if (q1d) {
            mO0 = rotd(sA0, t1, f1, tb13);  mO1 = rotd(sA1, t1, f1, tb13);
            mP0 = rotd(gA0, t1, f1, tb13);  mP1 = rotd(gA1, t1, f1, tb13);
          } else {
            float4 s1v = SM4[xx ^ 4096];
            float4 g1v = __ldcg(&PG4[xx ^ 4096]);
            float2 sB0 = make_float2(s1v.x, s1v.y), sB1 = make_float2(s1v.z, s1v.w);
            float2 gB0 = make_float2(g1v.x, g1v.y), gB1 = make_float2(g1v.z, g1v.w);
            mO0 = rotp(sA0, sB0, t1, f1, tb13);
            mO1 = rotp(sA1, sB1, t1, f1, tb13);
            mP0 = rotp(gA0, gB0, t1, f1, tb13);
            mP1 = rotp(gA1, gB1, t1, f1, tb13);
          }
          if (q0d) {
            a[2 * j]     = rotd(mO0, t0, f0, rank);
            a[2 * j + 1] = rotd(mP1, t0, f0, rank);
          } else {
            a[2 * j]     = rotp(mO0, mP0, t0, f0, rank);
            a[2 * j + 1] = rotp(mP1, mO1, t0, f0, rank);
          }
        }
      }
      // Rotations q2 (a bit3), q3 (bit2), q4 (bit1), q14 (bit0 = p).
      rotfac16<3>(a, st_t[g0 + 2],  st_f[g0 + 2]);
      rotfac16<2>(a, st_t[g0 + 3],  st_f[g0 + 3]);
      rotfac16<1>(a, st_t[g0 + 4],  st_f[g0 + 4]);
      rotfac16<0>(a, st_t[g0 + 14], st_f[g0 + 14]);
      // CNOT(1,2): ctrl = q1 post-CNOT(0,1) = tb13^rank (warp-uniform branch);
      // tgt q2 = a bit3.  (Conjugated control compensates for C01 at store.)
      if ((tb13 ^ rank) != 0) {
#pragma unroll
        for (int j2 = 0; j2 < 8; j2++) {
          float2 t2 = a[j2]; a[j2] = a[j2 | 8]; a[j2 | 8] = t2;
        }
      }
      cnotl16<3, 2>(a);  // CNOT(2,3)
      cnotl16<2, 1>(a);  // CNOT(3,4)
      // Store with fold: CNOT(0,1) -> addr ^ (rank<<13).
      // NOTE: CNOT(4,5) is NOT folded here — its target q5's rotation runs
      // in sweep B; the CNOT is applied there AFTER R_q5 (ring order).
      float4* SM4w = (float4*)SM;
      const int xS = xA ^ (rank << 12);
#pragma unroll
      for (int j = 0; j < 8; j++) {
        SM4w[xS | (j << 9)] =
            make_float4(a[2 * j].x, a[2 * j].y, a[2 * j + 1].x, a[2 * j + 1].y);
      }
    }
    __syncthreads();

    // ======== Sweep B: rotations q9 (pair-on-load), q5..q8, q10..q13 ========
    {
      const float t9 = st_t[g0 + 9]; const int f9 = st_f[g0 + 9];
      if (f9 >= 4) {
#pragma unroll
        for (int jb = 0; jb < 16; jb++)
          a[jb] = rotd(SM[baseB | (jb << 6)], t9, f9, wLo);
      } else {
#pragma unroll
        for (int jb = 0; jb < 16; jb++) {
          float2 own = SM[baseB | (jb << 6)];
          float2 par = SM[(baseB ^ 32) | (jb << 6)];
          a[jb] = rotp(own, par, t9, f9, wLo);
        }
      }
      // Rotations q5 (jb bit3), q6 (bit2), q7 (bit1), q8 (bit0).
      rotfac16<3>(a, st_t[g0 + 5], st_f[g0 + 5]);
      rotfac16<2>(a, st_t[g0 + 6], st_f[g0 + 6]);
      rotfac16<1>(a, st_t[g0 + 7], st_f[g0 + 7]);
      rotfac16<0>(a, st_t[g0 + 8], st_f[g0 + 8]);
      // Rotations q10..q13 (lane bits 4..1).  (q14 handled in sweep A.)
      rot_lane_fac16<4>(a, st_t[g0 + 10], st_f[g0 + 10], lane);
      rot_lane_fac16<3>(a, st_t[g0 + 11], st_f[g0 + 11], lane);
      rot_lane_fac16<2>(a, st_t[g0 + 12], st_f[g0 + 12], lane);
      rot_lane_fac16<1>(a, st_t[g0 + 13], st_f[g0 + 13], lane);
      // CNOT(4,5): ctrl q4 = amp bit10 = wHi bit0 = tid bit6 (warp-uniform
      // branch); tgt q5 = jb bit3. Applied AFTER R_q5 — ring order correct.
      if (wHi & 1) {
#pragma unroll
        for (int j2 = 0; j2 < 8; j2++) {
          float2 t2 = a[j2]; a[j2] = a[j2 | 8]; a[j2 | 8] = t2;
        }
      }
      cnotl16<3, 2>(a);  // CNOT(5,6)
      cnotl16<2, 1>(a);  // CNOT(6,7)
      cnotl16<1, 0>(a);  // CNOT(7,8)
      // CNOT(8,9): addr bit5 = wLo ^ (jb&1).
      // CNOT(9,10): cascade pre-flip by ctrl = wLo ^ (jb&1) -> dst ^ 31.
      // CNOT(10,11)..(13,14): cascade (dstE).
      // CNOT(14,0): physical, fused in next sweep-A load roles / reduction.

      if (l < N_LAYERS - 1) {
        // Dual write: SMEM (own next sweep A) + gmem (partner's next sweep A).
        float2* xw = (float2*)(g_xchg4
                       + ((size_t)(b * 2 + (l & 1)) * 2 + rank) * (NLOC / 2));
#pragma unroll
        for (int jb = 0; jb < 16; jb++) {
          const int c = wLo ^ (jb & 1);
          const int i = (wHi << 10) | (jb << 6) | (c << 5)
                        | (dstE ^ (c ? 31 : 0));
          SM[i] = a[jb];
          xw[i] = a[jb];
        }
        cluster.sync();
      } else {
        // |amp|^2 class reduction. Final q14 of reg jb = e0 ^ wLo ^ (jb&1);
        // q0 label flips (rank -> rank^1) when q14 = 1; q1 = tb13 (uniform).
        float pe = 0.f, po = 0.f;
#pragma unroll
        for (int jb = 0; jb < 16; jb++) {
          float p = fmaf(a[jb].x, a[jb].x, a[jb].y * a[jb].y);
          if (jb & 1) po += p; else pe += p;
        }
        const int g = e0 ^ wLo;    // q14 of even-jb amps
        pA = g ? po : pe;          // q0 label = rank
        pB = g ? pe : po;          // q0 label = rank^1
      }
    }
  }

  // ---- Reduce: full warp reduce (class meaning lane-uniform) -> CTA -> out --
#pragma unroll
  for (int o = 16; o > 0; o >>= 1) {
    pA += __shfl_xor_sync(0xffffffffu, pA, o);
    pB += __shfl_xor_sync(0xffffffffu, pB, o);
  }
  if (lane == 0) {
    atomicAdd(&sred[(rank << 1) | tb13], pA);
    atomicAdd(&sred[((rank ^ 1) << 1) | tb13], pB);
  }
  __syncthreads();

  if (rank == 1 && tid < 4) {
    float* dst = cluster.map_shared_rank(sred, 0);
    atomicAdd(dst + tid, sred[tid]);
  }
  cluster.sync();
  if (rank == 0 && tid < 4) out[b * 4 + tid] = sred[tid] * sS2;
}

extern "C" void kernel_launch(void* const* d_in, const int* in_sizes, int n_in,
                              void* d_out, int out_size) {
  const float* x    = (const float*)d_in[0];
  const float* P    = (const float*)d_in[1];
  const float* Q    = (const float*)d_in[2];
  const float* rotp = (const float*)d_in[3];
  const float* gum  = (const float*)d_in[4];
  cudaFuncSetAttribute(qdarts_kernel,
                       cudaFuncAttributeMaxDynamicSharedMemorySize,
                       (int)SMEM_BYTES);
  qdarts_kernel<<<BATCHN * 2, NTHREADS, SMEM_BYTES>>>(x, P, Q, rotp, gum,
                                                      (float*)d_out);
}